// round 14
// baseline (speedup 1.0000x reference)
#include <cuda_runtime.h>

#define T_STEPS 512
#define IN_F 5
#define HDIM 7
#define TS 64
#define NTILE (T_STEPS / TS)
#define XROW (TS * IN_F + 12)   // 332 words: bank spread, float4-aligned
#define OROW (TS * 4 + 4)       // 260 words

typedef unsigned long long u64;

__device__ __forceinline__ float tanh_ap(float a) {
    float r; asm("tanh.approx.f32 %0, %1;" : "=f"(r) : "f"(a)); return r;
}
__device__ __forceinline__ u64 pk(float lo, float hi) {
    u64 r; asm("mov.b64 %0, {%1, %2};" : "=l"(r) : "f"(lo), "f"(hi)); return r;
}
__device__ __forceinline__ u64 pk1(float v) { return pk(v, v); }
__device__ __forceinline__ void up(u64 v, float& lo, float& hi) {
    asm("mov.b64 {%0, %1}, %2;" : "=f"(lo), "=f"(hi) : "l"(v));
}
__device__ __forceinline__ u64 f2(u64 a, u64 b, u64 c) {
    u64 d; asm("fma.rn.f32x2 %0, %1, %2, %3;" : "=l"(d) : "l"(a), "l"(b), "l"(c)); return d;
}
__device__ __forceinline__ u64 a2(u64 a, u64 b) {
    u64 d; asm("add.rn.f32x2 %0, %1, %2;" : "=l"(d) : "l"(a), "l"(b)); return d;
}

// 1 warp/CTA; warp = 8 batches x 4 lanes; lane L owns units {2L, 2L+1} packed lo/hi.
// ROTATED GATHER: hall slot order per lane = [own0, own1, (L+1)-pair, (L+2)-pair,
// (L+3)-pair] -> only 6 SHFLs/step, own terms start the FMA chains early.
// All weight arrays are permuted per-lane to match this private ordering (dot
// products are order-invariant). Unit 7 = zero-weight slot wherever it falls.
// Gate algebra = 99us champion: r/z pre-halved, n h-side pre-halved, r eliminated.
__global__ void __launch_bounds__(32) gru_kernel(
    const float* __restrict__ x,
    const float* __restrict__ W_ih, const float* __restrict__ W_hh,
    const float* __restrict__ b_ih, const float* __restrict__ b_hh,
    const float* __restrict__ W_h0,
    const float* __restrict__ W_m, const float* __restrict__ b_m,
    const float* __restrict__ W_r, const float* __restrict__ b_r,
    float* __restrict__ out, int B)
{
    __shared__ __align__(16) float xs[8 * XROW];
    __shared__ __align__(16) float os[8 * OROW];

    int lane = threadIdx.x;
    int g = lane >> 2;
    int L = lane & 3;
    int b = blockIdx.x * 8 + g;

    float* out_m = out;
    float* out_r = out + (size_t)B * T_STEPS * 3;
    float* out_h = out + (size_t)B * T_STEPS * 4;

    // ---- per-lane hall-slot -> unit permutation ----
    int perm[8];
    perm[0] = 2 * L; perm[1] = 2 * L + 1;
#pragma unroll
    for (int d = 1; d < 4; d++) {
        perm[2 * d]     = 2 * ((L + d) & 3);
        perm[2 * d + 1] = 2 * ((L + d) & 3) + 1;
    }

    // ---- packed per-lane weights in PERMUTED slot order ----
    // lo/hi of each packed value = this lane's OWN unit pair (2L, 2L+1);
    // slot index s selects which h (unit perm[s]) multiplies it.
    u64 pwir[IN_F], pwiz[IN_F], pwin[IN_F];   // x-side (canonical, r/z pre-halved)
    u64 pwhr[8], pwhz[8], pwhn[8];            // h-side, slot-permuted, pre-halved
    u64 pbr, pbz, pbxn, pbhn;
    float wout[8], ob;                         // head weights, slot-permuted
    float h0s, h1s;
    {
        int u0 = 2 * L, u1 = 2 * L + 1;
        bool v1 = (u1 < HDIM);
        int r0 = u0, z0 = HDIM + u0, n0 = 2 * HDIM + u0;
        int r1 = u1, z1 = HDIM + u1, n1 = 2 * HDIM + u1;
#pragma unroll
        for (int i = 0; i < IN_F; i++) {
            pwir[i] = pk(0.5f * W_ih[r0 * IN_F + i], v1 ? 0.5f * W_ih[r1 * IN_F + i] : 0.f);
            pwiz[i] = pk(0.5f * W_ih[z0 * IN_F + i], v1 ? 0.5f * W_ih[z1 * IN_F + i] : 0.f);
            pwin[i] = pk(W_ih[n0 * IN_F + i], v1 ? W_ih[n1 * IN_F + i] : 0.f);
        }
#pragma unroll
        for (int s = 0; s < 8; s++) {
            int k = perm[s];
            bool vk = (k < HDIM);
            float wr0 = vk ? 0.5f * W_hh[r0 * HDIM + k] : 0.f;
            float wz0 = vk ? 0.5f * W_hh[z0 * HDIM + k] : 0.f;
            float wn0 = vk ? 0.5f * W_hh[n0 * HDIM + k] : 0.f;
            float wr1 = (vk && v1) ? 0.5f * W_hh[r1 * HDIM + k] : 0.f;
            float wz1 = (vk && v1) ? 0.5f * W_hh[z1 * HDIM + k] : 0.f;
            float wn1 = (vk && v1) ? 0.5f * W_hh[n1 * HDIM + k] : 0.f;
            pwhr[s] = pk(wr0, wr1);
            pwhz[s] = pk(wz0, wz1);
            pwhn[s] = pk(wn0, wn1);
            wout[s] = vk ? ((L < 3) ? W_m[L * HDIM + k] : W_r[k]) : 0.f;
        }
        pbr  = pk(0.5f * (b_ih[r0] + b_hh[r0]), v1 ? 0.5f * (b_ih[r1] + b_hh[r1]) : 0.f);
        pbz  = pk(0.5f * (b_ih[z0] + b_hh[z0]), v1 ? 0.5f * (b_ih[z1] + b_hh[z1]) : 0.f);
        pbxn = pk(b_ih[n0], v1 ? b_ih[n1] : 0.f);
        pbhn = pk(0.5f * b_hh[n0], v1 ? 0.5f * b_hh[n1] : 0.f);
        h0s = W_h0[u0];
        h1s = v1 ? W_h0[u1] : 0.f;
        ob  = (L < 3) ? b_m[L] : b_r[0];
    }

    const float* xb = x + (size_t)b * T_STEPS * IN_F;
    float* xrow = xs + g * XROW;
    float* orow = os + g * OROW;

    int s1 = (L + 1) & 3, s2 = (L + 2) & 3, s3 = (L + 3) & 3;

    // initial rotated gather (6 SHFLs; slots 0,1 are local)
    float hall[8];
    hall[0] = h0s; hall[1] = h1s;
    hall[2] = __shfl_sync(0xffffffffu, h0s, s1, 4);
    hall[3] = __shfl_sync(0xffffffffu, h1s, s1, 4);
    hall[4] = __shfl_sync(0xffffffffu, h0s, s2, 4);
    hall[5] = __shfl_sync(0xffffffffu, h1s, s2, 4);
    hall[6] = __shfl_sync(0xffffffffu, h0s, s3, 4);
    hall[7] = __shfl_sync(0xffffffffu, h1s, s3, 4);

    for (int tile = 0; tile < NTILE; tile++) {
        int t0 = tile * TS;

        // stage x tile (coalesced float4)
        __syncwarp();
        const float4* src = (const float4*)(xb + t0 * IN_F);
#pragma unroll
        for (int j = 0; j < (TS * IN_F) / 16; j++) {
            float4 v = src[L + 4 * j];
            *(float4*)(xrow + (L + 4 * j) * 4) = v;
        }
        __syncwarp();

        // preamble: packed projection of x[t0]; xvn = x[t0+1]
        u64 pxa_r, pxa_z, pxa_n;
        float xvn[IN_F];
        {
            u64 Ar = pbr, Az = pbz, An = pbxn;
#pragma unroll
            for (int i = 0; i < IN_F; i++) {
                u64 xi = pk1(xrow[i]);
                Ar = f2(pwir[i], xi, Ar);
                Az = f2(pwiz[i], xi, Az);
                An = f2(pwin[i], xi, An);
            }
            pxa_r = Ar; pxa_z = Az; pxa_n = An;
#pragma unroll
            for (int i = 0; i < IN_F; i++) xvn[i] = xrow[IN_F + i];
        }

#pragma unroll 2
        for (int tt = 0; tt < TS; tt++) {
            int t2 = (tt + 2 < TS) ? (tt + 2) : (TS - 1);
            float xv2[IN_F];
#pragma unroll
            for (int i = 0; i < IN_F; i++) xv2[i] = xrow[t2 * IN_F + i];

            // ---- packed gate dots: own slots (0,1) head the two accumulators ----
            u64 ph[8];
#pragma unroll
            for (int k = 0; k < 8; k++) ph[k] = pk1(hall[k]);

            u64 Ar0 = pxa_r, Ar1 = 0ULL;
            u64 Az0 = pxa_z, Az1 = 0ULL;
            u64 An0 = pbhn,  An1 = 0ULL;
#pragma unroll
            for (int k = 0; k < 8; k += 2) {
                Ar0 = f2(pwhr[k], ph[k], Ar0);         // k=0 is local h0s
                Az0 = f2(pwhz[k], ph[k], Az0);
                An0 = f2(pwhn[k], ph[k], An0);
                Ar1 = f2(pwhr[k + 1], ph[k + 1], Ar1); // k=1 is local h1s
                Az1 = f2(pwhz[k + 1], ph[k + 1], Az1);
                An1 = f2(pwhn[k + 1], ph[k + 1], An1);
            }
            u64 pAn = a2(An0, An1);        // An' = 0.5*hn (packed)
            u64 pc  = a2(pAn, pxa_n);      // c = xn + An' (packed)

            // ---- gates: r eliminated, z via 0.5+0.5*tanh ----
            float ar0, ar1, az0, az1, an0, an1, c0, c1;
            up(a2(Ar0, Ar1), ar0, ar1);
            up(a2(Az0, Az1), az0, az1);
            up(pAn, an0, an1);
            up(pc, c0, c1);

            float tr0 = tanh_ap(ar0), tr1 = tanh_ap(ar1);
            float tz0 = tanh_ap(az0), tz1 = tanh_ap(az1);
            float n0 = tanh_ap(fmaf(tr0, an0, c0));
            float n1 = tanh_ap(fmaf(tr1, an1, c1));
            float z0 = fmaf(0.5f, tz0, 0.5f);
            float z1 = fmaf(0.5f, tz1, 0.5f);
            h0s = fmaf(z0, h0s - n0, n0);
            h1s = fmaf(z1, h1s - n1, n1);

            // ---- rotated gather of h(t): 6 SHFLs, own pair local ----
            hall[0] = h0s; hall[1] = h1s;
            hall[2] = __shfl_sync(0xffffffffu, h0s, s1, 4);
            hall[3] = __shfl_sync(0xffffffffu, h1s, s1, 4);
            hall[4] = __shfl_sync(0xffffffffu, h0s, s2, 4);
            hall[5] = __shfl_sync(0xffffffffu, h1s, s2, 4);
            hall[6] = __shfl_sync(0xffffffffu, h0s, s3, 4);
            hall[7] = __shfl_sync(0xffffffffu, h1s, s3, 4);

            // ---- head (permuted weights, own terms first) ----
            float val = fmaf(wout[0], hall[0], ob);
#pragma unroll
            for (int k = 1; k < 8; k++) val = fmaf(wout[k], hall[k], val);
            orow[tt * 4 + L] = val;

            // ---- packed projection for step t+1 (off critical path) ----
            {
                u64 Ar = pbr, Az = pbz, An = pbxn;
#pragma unroll
                for (int i = 0; i < IN_F; i++) {
                    u64 xi = pk1(xvn[i]);
                    Ar = f2(pwir[i], xi, Ar);
                    Az = f2(pwiz[i], xi, Az);
                    An = f2(pwin[i], xi, An);
                }
                pxa_r = Ar; pxa_z = Az; pxa_n = An;
            }
#pragma unroll
            for (int i = 0; i < IN_F; i++) xvn[i] = xv2[i];
        }
        __syncwarp();

        // ---- flush out_m tile ----
        float* omg = out_m + (size_t)b * T_STEPS * 3 + t0 * 3;
#pragma unroll
        for (int q = 0; q < 12; q++) {
            int p = (4 * q + L) * 4;
            float4 v;
            v.x = orow[((p + 0) / 3) * 4 + (p + 0) % 3];
            v.y = orow[((p + 1) / 3) * 4 + (p + 1) % 3];
            v.z = orow[((p + 2) / 3) * 4 + (p + 2) % 3];
            v.w = orow[((p + 3) / 3) * 4 + (p + 3) % 3];
            *(float4*)(omg + p) = v;
        }
        // ---- flush out_r tile ----
        float* org = out_r + (size_t)b * T_STEPS + t0;
#pragma unroll
        for (int q = 0; q < 4; q++) {
            int p = (4 * q + L) * 4;
            float4 v;
            v.x = orow[(p + 0) * 4 + 3];
            v.y = orow[(p + 1) * 4 + 3];
            v.z = orow[(p + 2) * 4 + 3];
            v.w = orow[(p + 3) * 4 + 3];
            *(float4*)(org + p) = v;
        }
    }

    {
        int u0 = 2 * L, u1 = 2 * L + 1;
        out_h[(size_t)b * HDIM + u0] = h0s;
        if (u1 < HDIM) out_h[(size_t)b * HDIM + u1] = h1s;
    }
}

extern "C" void kernel_launch(void* const* d_in, const int* in_sizes, int n_in,
                              void* d_out, int out_size) {
    const float* x    = (const float*)d_in[0];
    const float* W_ih = (const float*)d_in[2];
    const float* W_hh = (const float*)d_in[3];
    const float* b_ih = (const float*)d_in[4];
    const float* b_hh = (const float*)d_in[5];
    const float* W_h0 = (const float*)d_in[6];
    const float* W_m  = (const float*)d_in[7];
    const float* b_m  = (const float*)d_in[8];
    const float* W_r  = (const float*)d_in[9];
    const float* b_r  = (const float*)d_in[10];

    int B = in_sizes[0] / (T_STEPS * IN_F);   // 8192
    int grid = (B + 7) / 8;                   // 8 batches per 1-warp CTA
    gru_kernel<<<grid, 32>>>(x, W_ih, W_hh, b_ih, b_hh, W_h0,
                             W_m, b_m, W_r, b_r, (float*)d_out, B);
}

// round 15
// speedup vs baseline: 1.0058x; 1.0058x over previous
#include <cuda_runtime.h>

#define T_STEPS 512
#define IN_F 5
#define HDIM 7
#define TS 64
#define NTILE (T_STEPS / TS)
#define XROW (TS * IN_F + 12)   // 332 words: %32==12 bank spread, float4-aligned
#define OROW (TS * 4 + 4)       // 260 words (aliased onto xs during flush)
#define HROW (TS * 8 + 4)       // 516 words: %32==4 bank spread, float4-aligned

typedef unsigned long long u64;

__device__ __forceinline__ float tanh_ap(float a) {
    float r; asm("tanh.approx.f32 %0, %1;" : "=f"(r) : "f"(a)); return r;
}
__device__ __forceinline__ u64 pk(float lo, float hi) {
    u64 r; asm("mov.b64 %0, {%1, %2};" : "=l"(r) : "f"(lo), "f"(hi)); return r;
}
__device__ __forceinline__ u64 pk1(float v) { return pk(v, v); }
__device__ __forceinline__ void up(u64 v, float& lo, float& hi) {
    asm("mov.b64 {%0, %1}, %2;" : "=f"(lo), "=f"(hi) : "l"(v));
}
__device__ __forceinline__ u64 f2(u64 a, u64 b, u64 c) {
    u64 d; asm("fma.rn.f32x2 %0, %1, %2, %3;" : "=l"(d) : "l"(a), "l"(b), "l"(c)); return d;
}
__device__ __forceinline__ u64 a2(u64 a, u64 b) {
    u64 d; asm("add.rn.f32x2 %0, %1, %2;" : "=l"(d) : "l"(a), "l"(b)); return d;
}

// 1 warp/CTA; warp = 8 batches x 4 lanes; lane L owns units {2L,2L+1} packed lo/hi
// (unit 7 dummy). Gate algebra = 99us champion (r/z pre-halved, n h-side pre-halved,
// r eliminated; dist-2 register prefetch of x; unroll 2).
// NEW: heads hoisted out of the recurrent loop. In-loop we stage the h-pair
// (STS.64 into hs); per tile a flush phase recomputes all 4 heads for 64 steps
// as packed dots (pure ILP, off the serial chain), then the float4 global flush
// runs from an os region aliased onto xs.
__global__ void __launch_bounds__(32) gru_kernel(
    const float* __restrict__ x,
    const float* __restrict__ W_ih, const float* __restrict__ W_hh,
    const float* __restrict__ b_ih, const float* __restrict__ b_hh,
    const float* __restrict__ W_h0,
    const float* __restrict__ W_m, const float* __restrict__ b_m,
    const float* __restrict__ W_r, const float* __restrict__ b_r,
    float* __restrict__ out, int B)
{
    __shared__ __align__(16) float xs[8 * XROW];   // x tile; aliased as os in flush
    __shared__ __align__(16) float hs[8 * HROW];   // staged h, 8 floats/step
    __shared__ __align__(16) u64 hw[18];           // warp-uniform packed head weights

    int lane = threadIdx.x;
    int g = lane >> 2;
    int L = lane & 3;
    int b = blockIdx.x * 8 + g;

    float* out_m = out;
    float* out_r = out + (size_t)B * T_STEPS * 3;
    float* out_h = out + (size_t)B * T_STEPS * 4;

    // ---- packed per-lane weights (lo = unit 2L, hi = unit 2L+1) ----
    u64 pwir[IN_F], pwiz[IN_F], pwin[IN_F];   // r,z pre-halved; n unhalved
    u64 pwhr[HDIM], pwhz[HDIM], pwhn[HDIM];   // all h-side pre-halved
    u64 pbr, pbz, pbxn, pbhn;
    float h0s, h1s;
    {
        int u0 = 2 * L, u1 = 2 * L + 1;
        bool v1 = (u1 < HDIM);
        int r0 = u0, z0 = HDIM + u0, n0 = 2 * HDIM + u0;
        int r1 = u1, z1 = HDIM + u1, n1 = 2 * HDIM + u1;
#pragma unroll
        for (int i = 0; i < IN_F; i++) {
            pwir[i] = pk(0.5f * W_ih[r0 * IN_F + i], v1 ? 0.5f * W_ih[r1 * IN_F + i] : 0.f);
            pwiz[i] = pk(0.5f * W_ih[z0 * IN_F + i], v1 ? 0.5f * W_ih[z1 * IN_F + i] : 0.f);
            pwin[i] = pk(W_ih[n0 * IN_F + i], v1 ? W_ih[n1 * IN_F + i] : 0.f);
        }
#pragma unroll
        for (int k = 0; k < HDIM; k++) {
            pwhr[k] = pk(0.5f * W_hh[r0 * HDIM + k], v1 ? 0.5f * W_hh[r1 * HDIM + k] : 0.f);
            pwhz[k] = pk(0.5f * W_hh[z0 * HDIM + k], v1 ? 0.5f * W_hh[z1 * HDIM + k] : 0.f);
            pwhn[k] = pk(0.5f * W_hh[n0 * HDIM + k], v1 ? 0.5f * W_hh[n1 * HDIM + k] : 0.f);
        }
        pbr  = pk(0.5f * (b_ih[r0] + b_hh[r0]), v1 ? 0.5f * (b_ih[r1] + b_hh[r1]) : 0.f);
        pbz  = pk(0.5f * (b_ih[z0] + b_hh[z0]), v1 ? 0.5f * (b_ih[z1] + b_hh[z1]) : 0.f);
        pbxn = pk(b_ih[n0], v1 ? b_ih[n1] : 0.f);
        pbhn = pk(0.5f * b_hh[n0], v1 ? 0.5f * b_hh[n1] : 0.f);
        h0s = W_h0[u0];
        h1s = v1 ? W_h0[u1] : 0.f;
    }

    // ---- warp-uniform head weights -> smem (loaded to regs per flush) ----
    // hw[k]    = pk(W_m[0][k], W_m[1][k])   k=0..7 (k==7 -> 0)
    // hw[8+k]  = pk(W_m[2][k], W_r[k])
    // hw[16]   = pk(b_m[0], b_m[1]); hw[17] = pk(b_m[2], b_r[0])
    if (lane < 8) {
        int k = lane;
        bool vk = (k < HDIM);
        hw[k]     = pk(vk ? W_m[0 * HDIM + k] : 0.f, vk ? W_m[1 * HDIM + k] : 0.f);
        hw[8 + k] = pk(vk ? W_m[2 * HDIM + k] : 0.f, vk ? W_r[k] : 0.f);
    }
    if (lane == 0) {
        hw[16] = pk(b_m[0], b_m[1]);
        hw[17] = pk(b_m[2], b_r[0]);
    }
    __syncwarp();

    const float* xb = x + (size_t)b * T_STEPS * IN_F;
    float* xrow = xs + g * XROW;
    float* hrow = hs + g * HROW;
    float* orow = xs + g * XROW;   // alias: os lives in xs during flush

    float hall[HDIM];
#pragma unroll
    for (int q = 0; q < 4; q++) {
        hall[2 * q] = __shfl_sync(0xffffffffu, h0s, q, 4);
        if (2 * q + 1 < HDIM)
            hall[2 * q + 1] = __shfl_sync(0xffffffffu, h1s, q, 4);
    }

    for (int tile = 0; tile < NTILE; tile++) {
        int t0 = tile * TS;

        // ---- stage x tile (coalesced float4) ----
        __syncwarp();
        const float4* src = (const float4*)(xb + t0 * IN_F);
#pragma unroll
        for (int j = 0; j < (TS * IN_F) / 16; j++) {
            float4 v = src[L + 4 * j];
            *(float4*)(xrow + (L + 4 * j) * 4) = v;
        }
        __syncwarp();

        // ---- preamble: packed projection of x[t0]; xvn = x[t0+1] ----
        u64 pxa_r, pxa_z, pxa_n;
        float xvn[IN_F];
        {
            u64 Ar = pbr, Az = pbz, An = pbxn;
#pragma unroll
            for (int i = 0; i < IN_F; i++) {
                u64 xi = pk1(xrow[i]);
                Ar = f2(pwir[i], xi, Ar);
                Az = f2(pwiz[i], xi, Az);
                An = f2(pwin[i], xi, An);
            }
            pxa_r = Ar; pxa_z = Az; pxa_n = An;
#pragma unroll
            for (int i = 0; i < IN_F; i++) xvn[i] = xrow[IN_F + i];
        }

#pragma unroll 2
        for (int tt = 0; tt < TS; tt++) {
            int t2 = (tt + 2 < TS) ? (tt + 2) : (TS - 1);
            float xv2[IN_F];
#pragma unroll
            for (int i = 0; i < IN_F; i++) xv2[i] = xrow[t2 * IN_F + i];

            // ---- packed gate dot-products over hall (2 accumulators) ----
            u64 ph[HDIM];
#pragma unroll
            for (int k = 0; k < HDIM; k++) ph[k] = pk1(hall[k]);

            u64 Ar0 = pxa_r, Ar1 = 0ULL;
            u64 Az0 = pxa_z, Az1 = 0ULL;
            u64 An0 = pbhn,  An1 = 0ULL;
#pragma unroll
            for (int k = 0; k < HDIM; k += 2) {
                Ar0 = f2(pwhr[k], ph[k], Ar0);
                Az0 = f2(pwhz[k], ph[k], Az0);
                An0 = f2(pwhn[k], ph[k], An0);
                if (k + 1 < HDIM) {
                    Ar1 = f2(pwhr[k + 1], ph[k + 1], Ar1);
                    Az1 = f2(pwhz[k + 1], ph[k + 1], Az1);
                    An1 = f2(pwhn[k + 1], ph[k + 1], An1);
                }
            }
            u64 pAn = a2(An0, An1);        // An' = 0.5*hn (packed)
            u64 pc  = a2(pAn, pxa_n);      // c = xn + An' (packed)

            // ---- gates: r eliminated, z via 0.5+0.5*tanh ----
            float ar0, ar1, az0, az1, an0, an1, c0, c1;
            up(a2(Ar0, Ar1), ar0, ar1);
            up(a2(Az0, Az1), az0, az1);
            up(pAn, an0, an1);
            up(pc, c0, c1);

            float tr0 = tanh_ap(ar0), tr1 = tanh_ap(ar1);
            float tz0 = tanh_ap(az0), tz1 = tanh_ap(az1);
            float n0 = tanh_ap(fmaf(tr0, an0, c0));
            float n1 = tanh_ap(fmaf(tr1, an1, c1));
            float z0 = fmaf(0.5f, tz0, 0.5f);
            float z1 = fmaf(0.5f, tz1, 0.5f);
            h0s = fmaf(z0, h0s - n0, n0);
            h1s = fmaf(z1, h1s - n1, n1);

            // ---- gather h(t) ----
#pragma unroll
            for (int q = 0; q < 4; q++) {
                hall[2 * q] = __shfl_sync(0xffffffffu, h0s, q, 4);
                if (2 * q + 1 < HDIM)
                    hall[2 * q + 1] = __shfl_sync(0xffffffffu, h1s, q, 4);
            }

            // ---- stage own h-pair (replaces in-loop head dot) ----
            {
                float2 st; st.x = h0s; st.y = h1s;
                *(float2*)(hrow + tt * 8 + 2 * L) = st;
            }

            // ---- packed projection for step t+1 (off critical path) ----
            {
                u64 Ar = pbr, Az = pbz, An = pbxn;
#pragma unroll
                for (int i = 0; i < IN_F; i++) {
                    u64 xi = pk1(xvn[i]);
                    Ar = f2(pwir[i], xi, Ar);
                    Az = f2(pwiz[i], xi, Az);
                    An = f2(pwin[i], xi, An);
                }
                pxa_r = Ar; pxa_z = Az; pxa_n = An;
            }
#pragma unroll
            for (int i = 0; i < IN_F; i++) xvn[i] = xv2[i];
        }
        __syncwarp();

        // ---- flush phase A: heads from staged h (pure ILP, off serial chain) ----
        {
            // load warp-uniform head weights (flush-local live range)
            u64 w01[8], w2r[8], b01, b2r;
#pragma unroll
            for (int k = 0; k < 8; k++) { w01[k] = hw[k]; w2r[k] = hw[8 + k]; }
            b01 = hw[16]; b2r = hw[17];

#pragma unroll 4
            for (int j = 0; j < TS / 4; j++) {
                int tt = 4 * j + L;
                float4 ha = *(float4*)(hrow + tt * 8);
                float4 hb = *(float4*)(hrow + tt * 8 + 4);
                float hv[8] = {ha.x, ha.y, ha.z, ha.w, hb.x, hb.y, hb.z, hb.w};
                u64 A = b01, C = b2r;
#pragma unroll
                for (int k = 0; k < 8; k++) {
                    u64 hk = pk1(hv[k]);
                    A = f2(w01[k], hk, A);
                    C = f2(w2r[k], hk, C);
                }
                float m0, m1, m2, rr;
                up(A, m0, m1);
                up(C, m2, rr);
                float4 st; st.x = m0; st.y = m1; st.z = m2; st.w = rr;
                *(float4*)(orow + tt * 4) = st;   // os layout [tt*4 + head], aliased in xs
            }
        }
        __syncwarp();

        // ---- flush phase B: coalesced float4 stores to global ----
        float* omg = out_m + (size_t)b * T_STEPS * 3 + t0 * 3;
#pragma unroll
        for (int q = 0; q < 12; q++) {
            int p = (4 * q + L) * 4;
            float4 v;
            v.x = orow[((p + 0) / 3) * 4 + (p + 0) % 3];
            v.y = orow[((p + 1) / 3) * 4 + (p + 1) % 3];
            v.z = orow[((p + 2) / 3) * 4 + (p + 2) % 3];
            v.w = orow[((p + 3) / 3) * 4 + (p + 3) % 3];
            *(float4*)(omg + p) = v;
        }
        float* org = out_r + (size_t)b * T_STEPS + t0;
#pragma unroll
        for (int q = 0; q < 4; q++) {
            int p = (4 * q + L) * 4;
            float4 v;
            v.x = orow[(p + 0) * 4 + 3];
            v.y = orow[(p + 1) * 4 + 3];
            v.z = orow[(p + 2) * 4 + 3];
            v.w = orow[(p + 3) * 4 + 3];
            *(float4*)(org + p) = v;
        }
    }

    {
        int u0 = 2 * L, u1 = 2 * L + 1;
        out_h[(size_t)b * HDIM + u0] = h0s;
        if (u1 < HDIM) out_h[(size_t)b * HDIM + u1] = h1s;
    }
}

extern "C" void kernel_launch(void* const* d_in, const int* in_sizes, int n_in,
                              void* d_out, int out_size) {
    const float* x    = (const float*)d_in[0];
    const float* W_ih = (const float*)d_in[2];
    const float* W_hh = (const float*)d_in[3];
    const float* b_ih = (const float*)d_in[4];
    const float* b_hh = (const float*)d_in[5];
    const float* W_h0 = (const float*)d_in[6];
    const float* W_m  = (const float*)d_in[7];
    const float* b_m  = (const float*)d_in[8];
    const float* W_r  = (const float*)d_in[9];
    const float* b_r  = (const float*)d_in[10];

    int B = in_sizes[0] / (T_STEPS * IN_F);   // 8192
    int grid = (B + 7) / 8;                   // 8 batches per 1-warp CTA
    gru_kernel<<<grid, 32>>>(x, W_ih, W_hh, b_ih, b_hh, W_h0,
                             W_m, b_m, W_r, b_r, (float*)d_out, B);
}

// round 17
// speedup vs baseline: 1.0239x; 1.0180x over previous
#include <cuda_runtime.h>

#define T_STEPS 512
#define IN_F 5
#define HDIM 7
#define TS 64
#define NTILE (T_STEPS / TS)
#define XROW2 (TS * IN_F * 2 + 12)  // 652 words: %32==12 bank spread, %4==0
#define OROW (TS * 4 + 4)           // 260 words

typedef unsigned long long u64;

__device__ __forceinline__ float tanh_ap(float a) {
    float r; asm("tanh.approx.f32 %0, %1;" : "=f"(r) : "f"(a)); return r;
}
__device__ __forceinline__ u64 pk(float lo, float hi) {
    u64 r; asm("mov.b64 %0, {%1, %2};" : "=l"(r) : "f"(lo), "f"(hi)); return r;
}
__device__ __forceinline__ u64 pk1(float v) { return pk(v, v); }
__device__ __forceinline__ void up(u64 v, float& lo, float& hi) {
    asm("mov.b64 {%0, %1}, %2;" : "=f"(lo), "=f"(hi) : "l"(v));
}
__device__ __forceinline__ u64 f2(u64 a, u64 b, u64 c) {
    u64 d; asm("fma.rn.f32x2 %0, %1, %2, %3;" : "=l"(d) : "l"(a), "l"(b), "l"(c)); return d;
}
__device__ __forceinline__ u64 a2(u64 a, u64 b) {
    u64 d; asm("add.rn.f32x2 %0, %1, %2;" : "=l"(d) : "l"(a), "l"(b)); return d;
}
__device__ __forceinline__ u64 lds64(const float* p) {
    u64 d; asm("ld.shared.b64 %0, [%1];" : "=l"(d)
               : "r"((unsigned)__cvta_generic_to_shared(p))); return d;
}

// 1 warp/CTA; warp = 8 batches x 4 lanes; lane L owns units {2L,2L+1} packed lo/hi
// (unit 7 dummy). Gate algebra = 99us champion (r/z pre-halved, n h-side pre-halved,
// r eliminated; unroll 2; in-loop heads).
// NEW vs champion: x tile stored DUPLICATED in smem ((x,x) pairs) so the packed
// projection reads its (x_i,x_i) operand with one LDS.64 — deletes 5 pk1 MOVs/step;
// dist-1 prefetch (load pairs at iteration top, consume at tail) — deletes the
// 5 register-shift MOVs/step of the old dist-2 scheme.
__global__ void __launch_bounds__(32) gru_kernel(
    const float* __restrict__ x,
    const float* __restrict__ W_ih, const float* __restrict__ W_hh,
    const float* __restrict__ b_ih, const float* __restrict__ b_hh,
    const float* __restrict__ W_h0,
    const float* __restrict__ W_m, const float* __restrict__ b_m,
    const float* __restrict__ W_r, const float* __restrict__ b_r,
    float* __restrict__ out, int B)
{
    __shared__ __align__(16) float xs[8 * XROW2];  // duplicated x tile
    __shared__ __align__(16) float os[8 * OROW];   // staged outputs

    int lane = threadIdx.x;
    int g = lane >> 2;
    int L = lane & 3;
    int b = blockIdx.x * 8 + g;

    float* out_m = out;
    float* out_r = out + (size_t)B * T_STEPS * 3;
    float* out_h = out + (size_t)B * T_STEPS * 4;

    // ---- packed per-lane weights (lo = unit 2L, hi = unit 2L+1) ----
    u64 pwir[IN_F], pwiz[IN_F], pwin[IN_F];   // r,z pre-halved; n unhalved
    u64 pwhr[HDIM], pwhz[HDIM], pwhn[HDIM];   // all h-side pre-halved
    u64 pbr, pbz, pbxn, pbhn;
    float h0s, h1s;
    {
        int u0 = 2 * L, u1 = 2 * L + 1;
        bool v1 = (u1 < HDIM);
        int r0 = u0, z0 = HDIM + u0, n0 = 2 * HDIM + u0;
        int r1 = u1, z1 = HDIM + u1, n1 = 2 * HDIM + u1;
#pragma unroll
        for (int i = 0; i < IN_F; i++) {
            pwir[i] = pk(0.5f * W_ih[r0 * IN_F + i], v1 ? 0.5f * W_ih[r1 * IN_F + i] : 0.f);
            pwiz[i] = pk(0.5f * W_ih[z0 * IN_F + i], v1 ? 0.5f * W_ih[z1 * IN_F + i] : 0.f);
            pwin[i] = pk(W_ih[n0 * IN_F + i], v1 ? W_ih[n1 * IN_F + i] : 0.f);
        }
#pragma unroll
        for (int k = 0; k < HDIM; k++) {
            pwhr[k] = pk(0.5f * W_hh[r0 * HDIM + k], v1 ? 0.5f * W_hh[r1 * HDIM + k] : 0.f);
            pwhz[k] = pk(0.5f * W_hh[z0 * HDIM + k], v1 ? 0.5f * W_hh[z1 * HDIM + k] : 0.f);
            pwhn[k] = pk(0.5f * W_hh[n0 * HDIM + k], v1 ? 0.5f * W_hh[n1 * HDIM + k] : 0.f);
        }
        pbr  = pk(0.5f * (b_ih[r0] + b_hh[r0]), v1 ? 0.5f * (b_ih[r1] + b_hh[r1]) : 0.f);
        pbz  = pk(0.5f * (b_ih[z0] + b_hh[z0]), v1 ? 0.5f * (b_ih[z1] + b_hh[z1]) : 0.f);
        pbxn = pk(b_ih[n0], v1 ? b_ih[n1] : 0.f);
        pbhn = pk(0.5f * b_hh[n0], v1 ? 0.5f * b_hh[n1] : 0.f);
        h0s = W_h0[u0];
        h1s = v1 ? W_h0[u1] : 0.f;
    }
    float wout[HDIM], ob;
#pragma unroll
    for (int k = 0; k < HDIM; k++)
        wout[k] = (L < 3) ? W_m[L * HDIM + k] : W_r[k];
    ob = (L < 3) ? b_m[L] : b_r[0];

    const float* xb = x + (size_t)b * T_STEPS * IN_F;
    float* xrow = xs + g * XROW2;
    float* orow = os + g * OROW;

    float hall[HDIM];
#pragma unroll
    for (int q = 0; q < 4; q++) {
        hall[2 * q] = __shfl_sync(0xffffffffu, h0s, q, 4);
        if (2 * q + 1 < HDIM)
            hall[2 * q + 1] = __shfl_sync(0xffffffffu, h1s, q, 4);
    }

    for (int tile = 0; tile < NTILE; tile++) {
        int t0 = tile * TS;

        // ---- stage x tile DUPLICATED: read float4, write two (x,x) float4s ----
        __syncwarp();
        const float4* src = (const float4*)(xb + t0 * IN_F);
#pragma unroll
        for (int j = 0; j < (TS * IN_F) / 16; j++) {   // 20
            float4 v = src[L + 4 * j];
            float4 d0; d0.x = v.x; d0.y = v.x; d0.z = v.y; d0.w = v.y;
            float4 d1; d1.x = v.z; d1.y = v.z; d1.z = v.w; d1.w = v.w;
            *(float4*)(xrow + (L + 4 * j) * 8)     = d0;
            *(float4*)(xrow + (L + 4 * j) * 8 + 4) = d1;
        }
        __syncwarp();

        // ---- preamble: packed projection of x[t0] straight from dup-pairs ----
        u64 pxa_r, pxa_z, pxa_n;
        {
            u64 Ar = pbr, Az = pbz, An = pbxn;
#pragma unroll
            for (int i = 0; i < IN_F; i++) {
                u64 xi = lds64(xrow + i * 2);
                Ar = f2(pwir[i], xi, Ar);
                Az = f2(pwiz[i], xi, Az);
                An = f2(pwin[i], xi, An);
            }
            pxa_r = Ar; pxa_z = Az; pxa_n = An;
        }

#pragma unroll 2
        for (int tt = 0; tt < TS; tt++) {
            // dist-1 prefetch: load x[t+1] pairs at top, consume in tail projection
            int t1 = (tt + 1 < TS) ? (tt + 1) : (TS - 1);
            u64 px[IN_F];
#pragma unroll
            for (int i = 0; i < IN_F; i++) px[i] = lds64(xrow + (t1 * IN_F + i) * 2);

            // ---- packed gate dot-products over hall (2 accumulators) ----
            u64 ph[HDIM];
#pragma unroll
            for (int k = 0; k < HDIM; k++) ph[k] = pk1(hall[k]);

            u64 Ar0 = pxa_r, Ar1 = 0ULL;
            u64 Az0 = pxa_z, Az1 = 0ULL;
            u64 An0 = pbhn,  An1 = 0ULL;
#pragma unroll
            for (int k = 0; k < HDIM; k += 2) {
                Ar0 = f2(pwhr[k], ph[k], Ar0);
                Az0 = f2(pwhz[k], ph[k], Az0);
                An0 = f2(pwhn[k], ph[k], An0);
                if (k + 1 < HDIM) {
                    Ar1 = f2(pwhr[k + 1], ph[k + 1], Ar1);
                    Az1 = f2(pwhz[k + 1], ph[k + 1], Az1);
                    An1 = f2(pwhn[k + 1], ph[k + 1], An1);
                }
            }
            u64 pAn = a2(An0, An1);        // An' = 0.5*hn (packed)
            u64 pc  = a2(pAn, pxa_n);      // c = xn + An' (packed)

            // ---- gates: r eliminated, z via 0.5+0.5*tanh ----
            float ar0, ar1, az0, az1, an0, an1, c0, c1;
            up(a2(Ar0, Ar1), ar0, ar1);
            up(a2(Az0, Az1), az0, az1);
            up(pAn, an0, an1);
            up(pc, c0, c1);

            float tr0 = tanh_ap(ar0), tr1 = tanh_ap(ar1);
            float tz0 = tanh_ap(az0), tz1 = tanh_ap(az1);
            float n0 = tanh_ap(fmaf(tr0, an0, c0));
            float n1 = tanh_ap(fmaf(tr1, an1, c1));
            float z0 = fmaf(0.5f, tz0, 0.5f);
            float z1 = fmaf(0.5f, tz1, 0.5f);
            h0s = fmaf(z0, h0s - n0, n0);
            h1s = fmaf(z1, h1s - n1, n1);

            // ---- gather h(t) + heads ----
#pragma unroll
            for (int q = 0; q < 4; q++) {
                hall[2 * q] = __shfl_sync(0xffffffffu, h0s, q, 4);
                if (2 * q + 1 < HDIM)
                    hall[2 * q + 1] = __shfl_sync(0xffffffffu, h1s, q, 4);
            }
            float val = ob;
#pragma unroll
            for (int k = 0; k < HDIM; k++) val = fmaf(wout[k], hall[k], val);
            orow[tt * 4 + L] = val;

            // ---- packed projection for step t+1 from prefetched pairs ----
            {
                u64 Ar = pbr, Az = pbz, An = pbxn;
#pragma unroll
                for (int i = 0; i < IN_F; i++) {
                    Ar = f2(pwir[i], px[i], Ar);
                    Az = f2(pwiz[i], px[i], Az);
                    An = f2(pwin[i], px[i], An);
                }
                pxa_r = Ar; pxa_z = Az; pxa_n = An;
            }
        }
        __syncwarp();

        // ---- flush out_m tile ----
        float* omg = out_m + (size_t)b * T_STEPS * 3 + t0 * 3;
#pragma unroll
        for (int q = 0; q < 12; q++) {
            int p = (4 * q + L) * 4;
            float4 v;
            v.x = orow[((p + 0) / 3) * 4 + (p + 0) % 3];
            v.y = orow[((p + 1) / 3) * 4 + (p + 1) % 3];
            v.z = orow[((p + 2) / 3) * 4 + (p + 2) % 3];
            v.w = orow[((p + 3) / 3) * 4 + (p + 3) % 3];
            *(float4*)(omg + p) = v;
        }
        // ---- flush out_r tile ----
        float* org = out_r + (size_t)b * T_STEPS + t0;
#pragma unroll
        for (int q = 0; q < 4; q++) {
            int p = (4 * q + L) * 4;
            float4 v;
            v.x = orow[(p + 0) * 4 + 3];
            v.y = orow[(p + 1) * 4 + 3];
            v.z = orow[(p + 2) * 4 + 3];
            v.w = orow[(p + 3) * 4 + 3];
            *(float4*)(org + p) = v;
        }
    }

    {
        int u0 = 2 * L, u1 = 2 * L + 1;
        out_h[(size_t)b * HDIM + u0] = h0s;
        if (u1 < HDIM) out_h[(size_t)b * HDIM + u1] = h1s;
    }
}

extern "C" void kernel_launch(void* const* d_in, const int* in_sizes, int n_in,
                              void* d_out, int out_size) {
    const float* x    = (const float*)d_in[0];
    const float* W_ih = (const float*)d_in[2];
    const float* W_hh = (const float*)d_in[3];
    const float* b_ih = (const float*)d_in[4];
    const float* b_hh = (const float*)d_in[5];
    const float* W_h0 = (const float*)d_in[6];
    const float* W_m  = (const float*)d_in[7];
    const float* b_m  = (const float*)d_in[8];
    const float* W_r  = (const float*)d_in[9];
    const float* b_r  = (const float*)d_in[10];

    int B = in_sizes[0] / (T_STEPS * IN_F);   // 8192
    int grid = (B + 7) / 8;                   // 8 batches per 1-warp CTA
    gru_kernel<<<grid, 32>>>(x, W_ih, W_hh, b_ih, b_hh, W_h0,
                             W_m, b_m, W_r, b_r, (float*)d_out, B);
}